// round 1
// baseline (speedup 1.0000x reference)
#include <cuda_runtime.h>
#include <cuda_bf16.h>
#include <math.h>
#include <stdint.h>

// ----------------------------------------------------------------------------
// Problem constants (fixed by the dataset)
// ----------------------------------------------------------------------------
#define NS   16384   // samples
#define INF_ 1024    // input features
#define H_   2048    // hidden
#define NC   10      // classes
#define PRIOR_VAR 100.0

// ----------------------------------------------------------------------------
// Scratch (static device globals — no allocations allowed)
// ----------------------------------------------------------------------------
__device__ __nv_bfloat16 g_Xb [NS * INF_];       // 32 MB
__device__ __nv_bfloat16 g_W1b[H_ * INF_];       //  4 MB
__device__ __nv_bfloat16 g_W2b[H_ * H_];         //  8 MB
__device__ __nv_bfloat16 g_h1 [(size_t)NS * H_]; // 64 MB
__device__ __nv_bfloat16 g_h2 [(size_t)NS * H_]; // 64 MB

// ----------------------------------------------------------------------------
// PTX helpers
// ----------------------------------------------------------------------------
__device__ __forceinline__ void cp16(uint32_t dst, const void* src) {
    asm volatile("cp.async.cg.shared.global [%0], [%1], 16;" :: "r"(dst), "l"(src));
}
__device__ __forceinline__ void cp_commit() {
    asm volatile("cp.async.commit_group;");
}
template<int N> __device__ __forceinline__ void cp_wait() {
    asm volatile("cp.async.wait_group %0;" :: "n"(N));
}
__device__ __forceinline__ void ldsm_x4(uint32_t* r, uint32_t addr) {
    asm volatile("ldmatrix.sync.aligned.m8n8.x4.shared.b16 {%0,%1,%2,%3}, [%4];"
                 : "=r"(r[0]), "=r"(r[1]), "=r"(r[2]), "=r"(r[3]) : "r"(addr));
}
__device__ __forceinline__ void ldsm_x2(uint32_t* r, uint32_t addr) {
    asm volatile("ldmatrix.sync.aligned.m8n8.x2.shared.b16 {%0,%1}, [%2];"
                 : "=r"(r[0]), "=r"(r[1]) : "r"(addr));
}
__device__ __forceinline__ void mma_bf16(float* d, const uint32_t* a, const uint32_t* b) {
    asm volatile("mma.sync.aligned.m16n8k16.row.col.f32.bf16.bf16.f32 "
                 "{%0,%1,%2,%3}, {%4,%5,%6,%7}, {%8,%9}, {%0,%1,%2,%3};"
                 : "+f"(d[0]), "+f"(d[1]), "+f"(d[2]), "+f"(d[3])
                 : "r"(a[0]), "r"(a[1]), "r"(a[2]), "r"(a[3]),
                   "r"(b[0]), "r"(b[1]));
}

// ----------------------------------------------------------------------------
// fp32 -> bf16 conversion (vectorized). dst: 0=g_Xb, 1=g_W1b, 2=g_W2b
// ----------------------------------------------------------------------------
__global__ void f2bf_kernel(const float* __restrict__ in, int n, int dst) {
    __nv_bfloat16* out = (dst == 0) ? g_Xb : ((dst == 1) ? g_W1b : g_W2b);
    int i = (blockIdx.x * blockDim.x + threadIdx.x) * 4;
    int stride = gridDim.x * blockDim.x * 4;
    for (; i + 3 < n; i += stride) {
        float4 v = *(const float4*)(in + i);
        __nv_bfloat162 lo = __floats2bfloat162_rn(v.x, v.y);
        __nv_bfloat162 hi = __floats2bfloat162_rn(v.z, v.w);
        *(__nv_bfloat162*)(out + i)     = lo;
        *(__nv_bfloat162*)(out + i + 2) = hi;
    }
}

// ----------------------------------------------------------------------------
// GEMM + bias + ReLU, bf16 inputs / fp32 accum / bf16 out.
//   C[M,N] = relu(A[M,K] @ W[N,K]^T + bias[N])
// 128x128x32 CTA tile, 8 warps (4x2), each warp 32x64 of m16n8k16 tiles.
// 2-stage cp.async pipeline. which: 0 = (g_Xb,g_W1b)->g_h1, 1 = (g_h1,g_W2b)->g_h2
// ----------------------------------------------------------------------------
__global__ __launch_bounds__(256, 2)
void gemm_bias_relu_kernel(int which, const float* __restrict__ bias,
                           int M, int N, int K)
{
    const __nv_bfloat16* __restrict__ A = (which == 0) ? g_Xb  : g_h1;
    const __nv_bfloat16* __restrict__ W = (which == 0) ? g_W1b : g_W2b;
    __nv_bfloat16* __restrict__ C       = (which == 0) ? g_h1  : g_h2;

    constexpr int BM = 128, BN = 128, BK = 32, LDS = 40;  // LDS padded: 80B rows
    __shared__ __nv_bfloat16 sA[2][BM * LDS];
    __shared__ __nv_bfloat16 sB[2][BN * LDS];

    const int tid  = threadIdx.x;
    const int lane = tid & 31;
    const int warp = tid >> 5;
    const int wm   = warp >> 1;   // 0..3
    const int wn   = warp & 1;    // 0..1
    const int bm   = blockIdx.y * BM;
    const int bn   = blockIdx.x * BN;

    float acc[2][8][4];
    #pragma unroll
    for (int i = 0; i < 2; i++)
        #pragma unroll
        for (int j = 0; j < 8; j++)
            #pragma unroll
            for (int q = 0; q < 4; q++) acc[i][j][q] = 0.f;

    const uint32_t saB = (uint32_t)__cvta_generic_to_shared(&sA[0][0]);
    const uint32_t sbB = (uint32_t)__cvta_generic_to_shared(&sB[0][0]);
    const uint32_t stBytes = BM * LDS * 2;  // per-stage bytes (same for A and B)

    const int KT = K / BK;

    // stage loader: 128 rows x 32 bf16 = 512 x 16B chunks per tile
    auto load_stage = [&](int kt, int s) {
        const int k0 = kt * BK;
        #pragma unroll
        for (int i = 0; i < 2; i++) {
            int t = tid + i * 256;
            int r = t >> 2;
            int c = (t & 3) * 8;
            cp16(saB + s * stBytes + (r * LDS + c) * 2,
                 A + (size_t)(bm + r) * K + k0 + c);
            cp16(sbB + s * stBytes + (r * LDS + c) * 2,
                 W + (size_t)(bn + r) * K + k0 + c);
        }
    };

    load_stage(0, 0);
    cp_commit();

    for (int kt = 0; kt < KT; kt++) {
        const int s = kt & 1;
        if (kt + 1 < KT) {
            load_stage(kt + 1, (kt + 1) & 1);
            cp_commit();
            cp_wait<1>();
        } else {
            cp_wait<0>();
        }
        __syncthreads();

        #pragma unroll
        for (int ks = 0; ks < 2; ks++) {
            uint32_t aF[2][4];
            #pragma unroll
            for (int mi = 0; mi < 2; mi++) {
                int r = wm * 32 + mi * 16 + (lane & 15);
                int c = ks * 16 + (lane >> 4) * 8;
                ldsm_x4(aF[mi], saB + s * stBytes + (r * LDS + c) * 2);
            }
            #pragma unroll
            for (int nj = 0; nj < 8; nj++) {
                uint32_t bF[2];
                int r16 = lane & 15;
                int nn  = wn * 64 + nj * 8 + (r16 & 7);
                int kk  = ks * 16 + (r16 >> 3) * 8;
                ldsm_x2(bF, sbB + s * stBytes + (nn * LDS + kk) * 2);
                #pragma unroll
                for (int mi = 0; mi < 2; mi++)
                    mma_bf16(acc[mi][nj], aF[mi], bF);
            }
        }
        __syncthreads();
    }

    // epilogue: bias + relu + bf16 store
    #pragma unroll
    for (int mi = 0; mi < 2; mi++) {
        int row0 = bm + wm * 32 + mi * 16 + (lane >> 2);
        #pragma unroll
        for (int nj = 0; nj < 8; nj++) {
            int col = bn + wn * 64 + nj * 8 + 2 * (lane & 3);
            float bv0 = bias[col], bv1 = bias[col + 1];
            float v0 = acc[mi][nj][0] + bv0; v0 = v0 < 0.f ? 0.f : v0;
            float v1 = acc[mi][nj][1] + bv1; v1 = v1 < 0.f ? 0.f : v1;
            float v2 = acc[mi][nj][2] + bv0; v2 = v2 < 0.f ? 0.f : v2;
            float v3 = acc[mi][nj][3] + bv1; v3 = v3 < 0.f ? 0.f : v3;
            *(__nv_bfloat162*)(C + (size_t)row0 * N + col) =
                __floats2bfloat162_rn(v0, v1);
            *(__nv_bfloat162*)(C + (size_t)(row0 + 8) * N + col) =
                __floats2bfloat162_rn(v2, v3);
        }
    }
}

// ----------------------------------------------------------------------------
// Fused head: logits = h2 @ W3^T + b3; sum log_softmax(logits)[Y].
// 16 rows per block (256 thr, warp = 2 rows). W3 staged to SMEM as bf16.
// ----------------------------------------------------------------------------
__global__ __launch_bounds__(256)
void loss_kernel(const float* __restrict__ W3, const float* __restrict__ b3,
                 const int* __restrict__ Y, float* __restrict__ out)
{
    __shared__ __nv_bfloat16 sW[NC * H_];
    __shared__ float sSum;
    const int tid = threadIdx.x;
    if (tid == 0) sSum = 0.f;
    for (int i = tid; i < NC * H_; i += 256)
        sW[i] = __float2bfloat16(W3[i]);
    __syncthreads();

    const int lane = tid & 31, warp = tid >> 5;
    float local = 0.f;
    #pragma unroll
    for (int rr = 0; rr < 2; rr++) {
        int row = blockIdx.x * 16 + warp * 2 + rr;
        const __nv_bfloat16* hr = g_h2 + (size_t)row * H_;
        float acc[NC];
        #pragma unroll
        for (int c = 0; c < NC; c++) acc[c] = 0.f;
        #pragma unroll 4
        for (int i = 0; i < H_ / 64; i++) {
            int k = i * 64 + lane * 2;
            __nv_bfloat162 hv = *(const __nv_bfloat162*)(hr + k);
            float fx = __bfloat162float(hv.x);
            float fy = __bfloat162float(hv.y);
            #pragma unroll
            for (int c = 0; c < NC; c++) {
                __nv_bfloat162 wv = *(const __nv_bfloat162*)(sW + c * H_ + k);
                acc[c] += fx * __bfloat162float(wv.x) + fy * __bfloat162float(wv.y);
            }
        }
        #pragma unroll
        for (int c = 0; c < NC; c++) {
            #pragma unroll
            for (int o = 16; o; o >>= 1)
                acc[c] += __shfl_xor_sync(0xFFFFFFFFu, acc[c], o);
        }
        if (lane == 0) {
            float lg[NC];
            float m = -1e30f;
            #pragma unroll
            for (int c = 0; c < NC; c++) {
                lg[c] = acc[c] + b3[c];
                m = fmaxf(m, lg[c]);
            }
            float se = 0.f;
            #pragma unroll
            for (int c = 0; c < NC; c++) se += expf(lg[c] - m);
            local += lg[Y[row]] - (m + logf(se));
        }
    }
    if (lane == 0) atomicAdd(&sSum, local);
    __syncthreads();
    if (tid == 0) atomicAdd(out, sSum);
}

// ----------------------------------------------------------------------------
// Prior: out += -0.5 * sum(p^2) / PRIOR_VAR   (constant term handled at init)
// ----------------------------------------------------------------------------
__global__ void sumsq_kernel(const float* __restrict__ p, int n, float* __restrict__ out) {
    float s = 0.f;
    for (int i = blockIdx.x * blockDim.x + threadIdx.x; i < n;
         i += gridDim.x * blockDim.x) {
        float v = p[i];
        s += v * v;
    }
    #pragma unroll
    for (int o = 16; o; o >>= 1) s += __shfl_xor_sync(0xFFFFFFFFu, s, o);
    __shared__ float ws[8];
    if ((threadIdx.x & 31) == 0) ws[threadIdx.x >> 5] = s;
    __syncthreads();
    if (threadIdx.x < 8) {
        float t = ws[threadIdx.x];
        #pragma unroll
        for (int o = 4; o; o >>= 1) t += __shfl_xor_sync(0xFFu, t, o);
        if (threadIdx.x == 0) atomicAdd(out, (float)(-0.5 / PRIOR_VAR) * t);
    }
}

__global__ void init_out_kernel(float* out, float c) { out[0] = c; }

// ----------------------------------------------------------------------------
// kernel_launch
// ----------------------------------------------------------------------------
extern "C" void kernel_launch(void* const* d_in, const int* in_sizes, int n_in,
                              void* d_out, int out_size)
{
    const float* X  = (const float*)d_in[0];
    const int*   Y  = (const int*)  d_in[1];
    const float* W1 = (const float*)d_in[2];
    const float* b1 = (const float*)d_in[3];
    const float* W2 = (const float*)d_in[4];
    const float* b2 = (const float*)d_in[5];
    const float* W3 = (const float*)d_in[6];
    const float* b3 = (const float*)d_in[7];
    float* out = (float*)d_out;

    // Prior constant term (d = total param count), computed in double on host.
    double d = 0.0;
    for (int i = 2; i < 8; i++) d += (double)in_sizes[i];
    float cterm = (float)(-0.5 * d * log(2.0 * M_PI * PRIOR_VAR));

    init_out_kernel<<<1, 1>>>(out, cterm);

    // Prior sum-of-squares over all parameter tensors.
    for (int i = 2; i < 8; i++) {
        int n = in_sizes[i];
        int blocks = (n + 256 * 8 - 1) / (256 * 8);
        if (blocks < 1) blocks = 1;
        sumsq_kernel<<<blocks, 256>>>((const float*)d_in[i], n, out);
    }

    // fp32 -> bf16 converts
    {
        int nX = NS * INF_;
        f2bf_kernel<<<(nX / 4 + 255) / 256, 256>>>(X, nX, 0);
        int n1 = H_ * INF_;
        f2bf_kernel<<<(n1 / 4 + 255) / 256, 256>>>(W1, n1, 1);
        int n2 = H_ * H_;
        f2bf_kernel<<<(n2 / 4 + 255) / 256, 256>>>(W2, n2, 2);
    }

    // GEMM1: h1 = relu(X @ W1^T + b1)   [16384, 2048], K=1024
    {
        dim3 grid(H_ / 128, NS / 128);
        gemm_bias_relu_kernel<<<grid, 256>>>(0, b1, NS, H_, INF_);
    }
    // GEMM2: h2 = relu(h1 @ W2^T + b2)  [16384, 2048], K=2048
    {
        dim3 grid(H_ / 128, NS / 128);
        gemm_bias_relu_kernel<<<grid, 256>>>(1, b2, NS, H_, H_);
    }

    // Head + log-softmax + LL accumulation
    loss_kernel<<<NS / 16, 256>>>(W3, b3, Y, out);
}

// round 3
// speedup vs baseline: 1.1381x; 1.1381x over previous
#include <cuda_runtime.h>
#include <cuda_bf16.h>
#include <cuda_fp8.h>
#include <math.h>
#include <stdint.h>

// ----------------------------------------------------------------------------
// Problem constants
// ----------------------------------------------------------------------------
#define NS   16384
#define INF_ 1024
#define H_   2048
#define NC   10
#define PRIOR_VAR 100.0

#define SCALE_W   64.0f    // W1,W2 stored as 64*W in e4m3
#define SCALE_H   8.0f     // h1 stored as 8*h1 in e4m3
#define INV_G1    (1.0f / SCALE_W)              // acc1 -> X@W1^T
#define INV_G2    (1.0f / (SCALE_W * SCALE_H))  // acc2 -> h1@W2^T

// ----------------------------------------------------------------------------
// Scratch (static device globals — no allocations allowed)
// ----------------------------------------------------------------------------
__device__ unsigned char g_Xq [NS * INF_];          // 16 MB  (X,  e4m3)
__device__ unsigned char g_W1q[H_ * INF_];          //  2 MB  (64*W1)
__device__ unsigned char g_W2q[H_ * H_];            //  4 MB  (64*W2)
__device__ unsigned char g_h1q[(size_t)NS * H_];    // 32 MB  (8*h1)
__device__ __nv_bfloat16 g_h2 [(size_t)NS * H_];    // 64 MB  (h2, bf16)

// ----------------------------------------------------------------------------
// PTX helpers
// ----------------------------------------------------------------------------
__device__ __forceinline__ void cp16(uint32_t dst, const void* src) {
    asm volatile("cp.async.cg.shared.global [%0], [%1], 16;" :: "r"(dst), "l"(src));
}
__device__ __forceinline__ void cp_commit() {
    asm volatile("cp.async.commit_group;");
}
template<int N> __device__ __forceinline__ void cp_wait() {
    asm volatile("cp.async.wait_group %0;" :: "n"(N));
}
__device__ __forceinline__ void ldsm_x4(uint32_t* r, uint32_t addr) {
    asm volatile("ldmatrix.sync.aligned.m8n8.x4.shared.b16 {%0,%1,%2,%3}, [%4];"
                 : "=r"(r[0]), "=r"(r[1]), "=r"(r[2]), "=r"(r[3]) : "r"(addr));
}
__device__ __forceinline__ void ldsm_x2(uint32_t* r, uint32_t addr) {
    asm volatile("ldmatrix.sync.aligned.m8n8.x2.shared.b16 {%0,%1}, [%2];"
                 : "=r"(r[0]), "=r"(r[1]) : "r"(addr));
}
// fp8 e4m3 MMA: m16n8k32, fp32 accumulate
__device__ __forceinline__ void mma_fp8(float* d, const uint32_t* a, const uint32_t* b) {
    asm volatile("mma.sync.aligned.m16n8k32.row.col.f32.e4m3.e4m3.f32 "
                 "{%0,%1,%2,%3}, {%4,%5,%6,%7}, {%8,%9}, {%0,%1,%2,%3};"
                 : "+f"(d[0]), "+f"(d[1]), "+f"(d[2]), "+f"(d[3])
                 : "r"(a[0]), "r"(a[1]), "r"(a[2]), "r"(a[3]),
                   "r"(b[0]), "r"(b[1]));
}
__device__ __forceinline__ unsigned char f2e4m3(float v) {
    return (unsigned char)__nv_cvt_float_to_fp8(v, __NV_SATFINITE, __NV_E4M3);
}

// ----------------------------------------------------------------------------
// FP8 GEMM + bias + activation.
//   which=0: g_h1q = fp8(8 * relu(Xq @ W1q^T / 64 + b1))        K=1024
//   which=1: g_h2  = bf16(relu(h1q @ W2q^T / 512 + b2))         K=2048
// CTA tile 128x128, BK=64 (bytes), 3-stage cp.async, 8 warps (4x2).
// SMEM rows padded to 80B (conflict-free ldmatrix phases).
// ----------------------------------------------------------------------------
#define BM 128
#define BN 128
#define BK 64
#define STAGES 3
#define ROWB 80
#define HALF_STG (BM * ROWB)           // 10240 (A), same for B
#define STG_BYTES (2 * HALF_STG)       // 20480
#define SMEM_DYN (STAGES * STG_BYTES)  // 61440

__global__ __launch_bounds__(256, 2)
void fp8_gemm_kernel(int which, const float* __restrict__ bias, int K)
{
    extern __shared__ unsigned char smem[];
    const unsigned char* __restrict__ A = (which == 0) ? g_Xq  : g_h1q;
    const unsigned char* __restrict__ B = (which == 0) ? g_W1q : g_W2q;

    uint32_t sb;
    asm("{ .reg .u64 t; cvta.to.shared.u64 t, %1; cvt.u32.u64 %0, t; }"
        : "=r"(sb) : "l"(smem));

    const int tid  = threadIdx.x;
    const int lane = tid & 31;
    const int warp = tid >> 5;
    const int wm   = warp >> 1;   // 0..3
    const int wn   = warp & 1;    // 0..1
    const int bm   = blockIdx.y * BM;
    const int bn   = blockIdx.x * BN;

    float acc[2][8][4];
    #pragma unroll
    for (int i = 0; i < 2; i++)
        #pragma unroll
        for (int j = 0; j < 8; j++)
            #pragma unroll
            for (int q = 0; q < 4; q++) acc[i][j][q] = 0.f;

    const int KT = K / BK;

    // one stage: A 128 rows x 64B + B 128 rows x 64B, 16B chunks
    auto load_stage = [&](int st, int kt) {
        uint32_t aB = sb + st * STG_BYTES;
        uint32_t bB = aB + HALF_STG;
        const unsigned char* Ap = A + (size_t)bm * K + kt * BK;
        const unsigned char* Bp = B + (size_t)bn * K + kt * BK;
        #pragma unroll
        for (int q = 0; q < 2; q++) {
            int idx = tid + q * 256;
            int r = idx >> 2, c = (idx & 3) * 16;
            cp16(aB + r * ROWB + c, Ap + (size_t)r * K + c);
            cp16(bB + r * ROWB + c, Bp + (size_t)r * K + c);
        }
    };

    #pragma unroll
    for (int p = 0; p < STAGES - 1; p++) { load_stage(p, p); cp_commit(); }

    for (int i = 0; i < KT; i++) {
        const int s = i % STAGES;
        cp_wait<STAGES - 2>();
        __syncthreads();
        if (i + STAGES - 1 < KT) load_stage((i + STAGES - 1) % STAGES, i + STAGES - 1);
        cp_commit();

        const uint32_t aBase = sb + s * STG_BYTES;
        const uint32_t bBase = aBase + HALF_STG;
        #pragma unroll
        for (int ks = 0; ks < 2; ks++) {          // two k32 steps per BK=64
            uint32_t aF[2][4];
            #pragma unroll
            for (int mi = 0; mi < 2; mi++) {
                int r = wm * 32 + mi * 16 + (lane & 15);
                int c = ks * 32 + (lane >> 4) * 16;   // bytes
                ldsm_x4(aF[mi], aBase + r * ROWB + c);
            }
            #pragma unroll
            for (int nj = 0; nj < 8; nj++) {
                uint32_t bF[2];
                int r16 = lane & 15;
                int nn  = wn * 64 + nj * 8 + (r16 & 7);
                int kk  = ks * 32 + (r16 >> 3) * 16;  // bytes
                ldsm_x2(bF, bBase + nn * ROWB + kk);
                #pragma unroll
                for (int mi = 0; mi < 2; mi++)
                    mma_fp8(acc[mi][nj], aF[mi], bF);
            }
        }
    }

    // epilogue
    const float inv = (which == 0) ? INV_G1 : INV_G2;
    #pragma unroll
    for (int mi = 0; mi < 2; mi++) {
        int row0 = bm + wm * 32 + mi * 16 + (lane >> 2);
        #pragma unroll
        for (int nj = 0; nj < 8; nj++) {
            int col = bn + wn * 64 + nj * 8 + 2 * (lane & 3);
            float bv0 = __ldg(bias + col), bv1 = __ldg(bias + col + 1);
            float v0 = fmaxf(acc[mi][nj][0] * inv + bv0, 0.f);
            float v1 = fmaxf(acc[mi][nj][1] * inv + bv1, 0.f);
            float v2 = fmaxf(acc[mi][nj][2] * inv + bv0, 0.f);
            float v3 = fmaxf(acc[mi][nj][3] * inv + bv1, 0.f);
            if (which == 0) {
                unsigned short p0 = (unsigned short)f2e4m3(v0 * SCALE_H) |
                                    ((unsigned short)f2e4m3(v1 * SCALE_H) << 8);
                unsigned short p1 = (unsigned short)f2e4m3(v2 * SCALE_H) |
                                    ((unsigned short)f2e4m3(v3 * SCALE_H) << 8);
                *(unsigned short*)(g_h1q + (size_t)row0 * H_ + col)       = p0;
                *(unsigned short*)(g_h1q + (size_t)(row0 + 8) * H_ + col) = p1;
            } else {
                *(__nv_bfloat162*)(g_h2 + (size_t)row0 * H_ + col) =
                    __floats2bfloat162_rn(v0, v1);
                *(__nv_bfloat162*)(g_h2 + (size_t)(row0 + 8) * H_ + col) =
                    __floats2bfloat162_rn(v2, v3);
            }
        }
    }
}

// ----------------------------------------------------------------------------
// Fused fp32 -> fp8 convert (with scale) + optional prior sum-of-squares.
// dst: 0=g_Xq, 1=g_W1q, 2=g_W2q, 3=no convert.
// ----------------------------------------------------------------------------
__global__ void conv_sumsq_kernel(const float* __restrict__ in, int n,
                                  int dst, float scale, int do_sum,
                                  float* __restrict__ out)
{
    unsigned char* o = (dst == 0) ? g_Xq : (dst == 1) ? g_W1q
                     : (dst == 2) ? g_W2q : nullptr;
    float s = 0.f;
    const int gsz = gridDim.x * blockDim.x;
    const int gt  = blockIdx.x * blockDim.x + threadIdx.x;
    const int n4  = n >> 2;
    for (int i = gt; i < n4; i += gsz) {
        float4 v = ((const float4*)in)[i];
        if (o) {
            uint32_t p = (uint32_t)f2e4m3(v.x * scale)
                       | ((uint32_t)f2e4m3(v.y * scale) << 8)
                       | ((uint32_t)f2e4m3(v.z * scale) << 16)
                       | ((uint32_t)f2e4m3(v.w * scale) << 24);
            ((uint32_t*)o)[i] = p;
        }
        s += v.x * v.x + v.y * v.y + v.z * v.z + v.w * v.w;
    }
    for (int i = 4 * n4 + gt; i < n; i += gsz) {
        float v = in[i];
        if (o) o[i] = f2e4m3(v * scale);
        s += v * v;
    }
    if (!do_sum) return;
    #pragma unroll
    for (int ofs = 16; ofs; ofs >>= 1) s += __shfl_xor_sync(0xFFFFFFFFu, s, ofs);
    __shared__ float ws[8];
    if ((threadIdx.x & 31) == 0) ws[threadIdx.x >> 5] = s;
    __syncthreads();
    if (threadIdx.x < 8) {
        float t = ws[threadIdx.x];
        #pragma unroll
        for (int ofs = 4; ofs; ofs >>= 1) t += __shfl_xor_sync(0xFFu, t, ofs);
        if (threadIdx.x == 0) atomicAdd(out, (float)(-0.5 / PRIOR_VAR) * t);
    }
}

// ----------------------------------------------------------------------------
// Fused head: logits = h2 @ W3^T + b3; sum log_softmax(logits)[Y].
// ----------------------------------------------------------------------------
__global__ __launch_bounds__(256)
void loss_kernel(const float* __restrict__ W3, const float* __restrict__ b3,
                 const int* __restrict__ Y, float* __restrict__ out)
{
    __shared__ __nv_bfloat16 sW[NC * H_];
    __shared__ float sSum;
    const int tid = threadIdx.x;
    if (tid == 0) sSum = 0.f;
    for (int i = tid; i < NC * H_; i += 256)
        sW[i] = __float2bfloat16(W3[i]);
    __syncthreads();

    const int lane = tid & 31, warp = tid >> 5;
    float local = 0.f;
    #pragma unroll
    for (int rr = 0; rr < 2; rr++) {
        int row = blockIdx.x * 16 + warp * 2 + rr;
        const __nv_bfloat16* hr = g_h2 + (size_t)row * H_;
        float acc[NC];
        #pragma unroll
        for (int c = 0; c < NC; c++) acc[c] = 0.f;
        #pragma unroll 4
        for (int i = 0; i < H_ / 64; i++) {
            int k = i * 64 + lane * 2;
            __nv_bfloat162 hv = *(const __nv_bfloat162*)(hr + k);
            float fx = __bfloat162float(hv.x);
            float fy = __bfloat162float(hv.y);
            #pragma unroll
            for (int c = 0; c < NC; c++) {
                __nv_bfloat162 wv = *(const __nv_bfloat162*)(sW + c * H_ + k);
                acc[c] += fx * __bfloat162float(wv.x) + fy * __bfloat162float(wv.y);
            }
        }
        #pragma unroll
        for (int c = 0; c < NC; c++) {
            #pragma unroll
            for (int o = 16; o; o >>= 1)
                acc[c] += __shfl_xor_sync(0xFFFFFFFFu, acc[c], o);
        }
        if (lane == 0) {
            float lg[NC];
            float m = -1e30f;
            #pragma unroll
            for (int c = 0; c < NC; c++) {
                lg[c] = acc[c] + b3[c];
                m = fmaxf(m, lg[c]);
            }
            float se = 0.f;
            #pragma unroll
            for (int c = 0; c < NC; c++) se += expf(lg[c] - m);
            local += lg[Y[row]] - (m + logf(se));
        }
    }
    if (lane == 0) atomicAdd(&sSum, local);
    __syncthreads();
    if (tid == 0) atomicAdd(out, sSum);
}

__global__ void init_out_kernel(float* out, float c) { out[0] = c; }

// ----------------------------------------------------------------------------
// kernel_launch
// ----------------------------------------------------------------------------
extern "C" void kernel_launch(void* const* d_in, const int* in_sizes, int n_in,
                              void* d_out, int out_size)
{
    const float* X  = (const float*)d_in[0];
    const int*   Y  = (const int*)  d_in[1];
    const float* W1 = (const float*)d_in[2];
    const float* b1 = (const float*)d_in[3];
    const float* W2 = (const float*)d_in[4];
    const float* b2 = (const float*)d_in[5];
    const float* W3 = (const float*)d_in[6];
    const float* b3 = (const float*)d_in[7];
    float* out = (float*)d_out;

    cudaFuncSetAttribute(fp8_gemm_kernel,
                         cudaFuncAttributeMaxDynamicSharedMemorySize, SMEM_DYN);

    double d = 0.0;
    for (int i = 2; i < 8; i++) d += (double)in_sizes[i];
    float cterm = (float)(-0.5 * d * log(2.0 * M_PI * PRIOR_VAR));
    init_out_kernel<<<1, 1>>>(out, cterm);

    auto conv_grid = [](int n) {
        int g = (n / 4 + 255) / 256;
        if (g < 1) g = 1;
        if (g > 4096) g = 4096;
        return g;
    };
    conv_sumsq_kernel<<<conv_grid(NS * INF_), 256>>>(X,  NS * INF_, 0, 1.0f,    0, out);
    conv_sumsq_kernel<<<conv_grid(H_ * INF_), 256>>>(W1, H_ * INF_, 1, SCALE_W, 1, out);
    conv_sumsq_kernel<<<conv_grid(H_ * H_),   256>>>(W2, H_ * H_,   2, SCALE_W, 1, out);
    conv_sumsq_kernel<<<conv_grid(in_sizes[3]), 256>>>(b1, in_sizes[3], 3, 0.f, 1, out);
    conv_sumsq_kernel<<<conv_grid(in_sizes[5]), 256>>>(b2, in_sizes[5], 3, 0.f, 1, out);
    conv_sumsq_kernel<<<conv_grid(in_sizes[6]), 256>>>(W3, in_sizes[6], 3, 0.f, 1, out);
    conv_sumsq_kernel<<<conv_grid(in_sizes[7]), 256>>>(b3, in_sizes[7], 3, 0.f, 1, out);

    dim3 grid(H_ / BN, NS / BM);  // (16, 128)
    fp8_gemm_kernel<<<grid, 256, SMEM_DYN>>>(0, b1, INF_);
    fp8_gemm_kernel<<<grid, 256, SMEM_DYN>>>(1, b2, H_);

    loss_kernel<<<NS / 16, 256>>>(W3, b3, Y, out);
}

// round 4
// speedup vs baseline: 1.1732x; 1.0308x over previous
#include <cuda_runtime.h>
#include <cuda_bf16.h>
#include <cuda_fp16.h>
#include <cuda_fp8.h>
#include <math.h>
#include <stdint.h>

// ----------------------------------------------------------------------------
// Problem constants
// ----------------------------------------------------------------------------
#define NS   16384
#define INF_ 1024
#define H_   2048
#define NC   10
#define PRIOR_VAR 100.0

#define SCALE_W   64.0f    // W1,W2 stored as 64*W in e4m3
#define SCALE_H   8.0f     // h1 stored as 8*h1 in e4m3
#define INV_G1    (1.0f / SCALE_W)              // acc1 -> X@W1^T
#define INV_G2    (1.0f / (SCALE_W * SCALE_H))  // acc2 -> h1@W2^T

// ----------------------------------------------------------------------------
// Scratch (static device globals — no allocations allowed)
// ----------------------------------------------------------------------------
__device__ unsigned char g_Xq [NS * INF_];          // 16 MB
__device__ unsigned char g_W1q[H_ * INF_];          //  2 MB
__device__ unsigned char g_W2q[H_ * H_];            //  4 MB
__device__ unsigned char g_h1q[(size_t)NS * H_];    // 32 MB
__device__ __nv_bfloat16 g_h2 [(size_t)NS * H_];    // 64 MB

// ----------------------------------------------------------------------------
// PTX helpers
// ----------------------------------------------------------------------------
__device__ __forceinline__ void cp16(uint32_t dst, const void* src) {
    asm volatile("cp.async.cg.shared.global [%0], [%1], 16;" :: "r"(dst), "l"(src));
}
__device__ __forceinline__ void cp_commit() {
    asm volatile("cp.async.commit_group;");
}
template<int N> __device__ __forceinline__ void cp_wait() {
    asm volatile("cp.async.wait_group %0;" :: "n"(N));
}
__device__ __forceinline__ void ldsm_x4(uint32_t* r, uint32_t addr) {
    asm volatile("ldmatrix.sync.aligned.m8n8.x4.shared.b16 {%0,%1,%2,%3}, [%4];"
                 : "=r"(r[0]), "=r"(r[1]), "=r"(r[2]), "=r"(r[3]) : "r"(addr));
}
__device__ __forceinline__ void ldsm_x2(uint32_t* r, uint32_t addr) {
    asm volatile("ldmatrix.sync.aligned.m8n8.x2.shared.b16 {%0,%1}, [%2];"
                 : "=r"(r[0]), "=r"(r[1]) : "r"(addr));
}
// fp8 e4m3 MMA, fp16 accumulate: D(2xf16x2) = A(4) * B(2) + D
__device__ __forceinline__ void mma_fp8_h(uint32_t* d, const uint32_t* a,
                                          const uint32_t* b) {
    asm volatile("mma.sync.aligned.m16n8k32.row.col.f16.e4m3.e4m3.f16 "
                 "{%0,%1}, {%2,%3,%4,%5}, {%6,%7}, {%0,%1};"
                 : "+r"(d[0]), "+r"(d[1])
                 : "r"(a[0]), "r"(a[1]), "r"(a[2]), "r"(a[3]),
                   "r"(b[0]), "r"(b[1]));
}
__device__ __forceinline__ unsigned char f2e4m3(float v) {
    return (unsigned char)__nv_cvt_float_to_fp8(v, __NV_SATFINITE, __NV_E4M3);
}

// ----------------------------------------------------------------------------
// FP8 GEMM (f16 accum) + bias + activation.
//   which=0: g_h1q = fp8(8 * relu(Xq @ W1q^T / 64 + b1))        K=1024
//   which=1: g_h2  = bf16(relu(h1q @ W2q^T / 512 + b2))         K=2048
// CTA tile 128x128, BK=64 bytes, 3-stage cp.async, 8 warps (4x2).
// ----------------------------------------------------------------------------
#define BM 128
#define BN 128
#define BK 64
#define STAGES 3
#define ROWB 80
#define HALF_STG (BM * ROWB)
#define STG_BYTES (2 * HALF_STG)
#define SMEM_DYN (STAGES * STG_BYTES)  // 61440

__global__ __launch_bounds__(256, 2)
void fp8_gemm_kernel(int which, const float* __restrict__ bias, int K)
{
    extern __shared__ unsigned char smem[];
    const unsigned char* __restrict__ A = (which == 0) ? g_Xq  : g_h1q;
    const unsigned char* __restrict__ B = (which == 0) ? g_W1q : g_W2q;

    uint32_t sb;
    asm("{ .reg .u64 t; cvta.to.shared.u64 t, %1; cvt.u32.u64 %0, t; }"
        : "=r"(sb) : "l"(smem));

    const int tid  = threadIdx.x;
    const int lane = tid & 31;
    const int warp = tid >> 5;
    const int wm   = warp >> 1;
    const int wn   = warp & 1;
    const int bm   = blockIdx.y * BM;
    const int bn   = blockIdx.x * BN;

    uint32_t acc[2][8][2];   // f16x2 accumulators
    #pragma unroll
    for (int i = 0; i < 2; i++)
        #pragma unroll
        for (int j = 0; j < 8; j++) { acc[i][j][0] = 0u; acc[i][j][1] = 0u; }

    const int KT = K / BK;

    auto load_stage = [&](int st, int kt) {
        uint32_t aB = sb + st * STG_BYTES;
        uint32_t bB = aB + HALF_STG;
        const unsigned char* Ap = A + (size_t)bm * K + kt * BK;
        const unsigned char* Bp = B + (size_t)bn * K + kt * BK;
        #pragma unroll
        for (int q = 0; q < 2; q++) {
            int idx = tid + q * 256;
            int r = idx >> 2, c = (idx & 3) * 16;
            cp16(aB + r * ROWB + c, Ap + (size_t)r * K + c);
            cp16(bB + r * ROWB + c, Bp + (size_t)r * K + c);
        }
    };

    #pragma unroll
    for (int p = 0; p < STAGES - 1; p++) { load_stage(p, p); cp_commit(); }

    for (int i = 0; i < KT; i++) {
        const int s = i % STAGES;
        cp_wait<STAGES - 2>();
        __syncthreads();
        if (i + STAGES - 1 < KT) load_stage((i + STAGES - 1) % STAGES, i + STAGES - 1);
        cp_commit();

        const uint32_t aBase = sb + s * STG_BYTES;
        const uint32_t bBase = aBase + HALF_STG;
        #pragma unroll
        for (int ks = 0; ks < 2; ks++) {
            uint32_t aF[2][4];
            #pragma unroll
            for (int mi = 0; mi < 2; mi++) {
                int r = wm * 32 + mi * 16 + (lane & 15);
                int c = ks * 32 + (lane >> 4) * 16;
                ldsm_x4(aF[mi], aBase + r * ROWB + c);
            }
            #pragma unroll
            for (int nj = 0; nj < 8; nj++) {
                uint32_t bF[2];
                int r16 = lane & 15;
                int nn  = wn * 64 + nj * 8 + (r16 & 7);
                int kk  = ks * 32 + (r16 >> 3) * 16;
                ldsm_x2(bF, bBase + nn * ROWB + kk);
                #pragma unroll
                for (int mi = 0; mi < 2; mi++)
                    mma_fp8_h(acc[mi][nj], aF[mi], bF);
            }
        }
    }

    // epilogue
    const float inv = (which == 0) ? INV_G1 : INV_G2;
    #pragma unroll
    for (int mi = 0; mi < 2; mi++) {
        int row0 = bm + wm * 32 + mi * 16 + (lane >> 2);
        #pragma unroll
        for (int nj = 0; nj < 8; nj++) {
            int col = bn + wn * 64 + nj * 8 + 2 * (lane & 3);
            float bv0 = __ldg(bias + col), bv1 = __ldg(bias + col + 1);
            float2 f01 = __half22float2(*(const __half2*)&acc[mi][nj][0]);
            float2 f23 = __half22float2(*(const __half2*)&acc[mi][nj][1]);
            float v0 = fmaxf(f01.x * inv + bv0, 0.f);
            float v1 = fmaxf(f01.y * inv + bv1, 0.f);
            float v2 = fmaxf(f23.x * inv + bv0, 0.f);
            float v3 = fmaxf(f23.y * inv + bv1, 0.f);
            if (which == 0) {
                unsigned short p0 = (unsigned short)f2e4m3(v0 * SCALE_H) |
                                    ((unsigned short)f2e4m3(v1 * SCALE_H) << 8);
                unsigned short p1 = (unsigned short)f2e4m3(v2 * SCALE_H) |
                                    ((unsigned short)f2e4m3(v3 * SCALE_H) << 8);
                *(unsigned short*)(g_h1q + (size_t)row0 * H_ + col)       = p0;
                *(unsigned short*)(g_h1q + (size_t)(row0 + 8) * H_ + col) = p1;
            } else {
                *(__nv_bfloat162*)(g_h2 + (size_t)row0 * H_ + col) =
                    __floats2bfloat162_rn(v0, v1);
                *(__nv_bfloat162*)(g_h2 + (size_t)(row0 + 8) * H_ + col) =
                    __floats2bfloat162_rn(v2, v3);
            }
        }
    }
}

// ----------------------------------------------------------------------------
// Fused fp32 -> fp8 convert (with scale) + optional prior sum-of-squares.
// ----------------------------------------------------------------------------
__global__ void conv_sumsq_kernel(const float* __restrict__ in, int n,
                                  int dst, float scale, int do_sum,
                                  float* __restrict__ out)
{
    unsigned char* o = (dst == 0) ? g_Xq : (dst == 1) ? g_W1q
                     : (dst == 2) ? g_W2q : nullptr;
    float s = 0.f;
    const int gsz = gridDim.x * blockDim.x;
    const int gt  = blockIdx.x * blockDim.x + threadIdx.x;
    const int n4  = n >> 2;
    for (int i = gt; i < n4; i += gsz) {
        float4 v = ((const float4*)in)[i];
        if (o) {
            uint32_t p = (uint32_t)f2e4m3(v.x * scale)
                       | ((uint32_t)f2e4m3(v.y * scale) << 8)
                       | ((uint32_t)f2e4m3(v.z * scale) << 16)
                       | ((uint32_t)f2e4m3(v.w * scale) << 24);
            ((uint32_t*)o)[i] = p;
        }
        s += v.x * v.x + v.y * v.y + v.z * v.z + v.w * v.w;
    }
    for (int i = 4 * n4 + gt; i < n; i += gsz) {
        float v = in[i];
        if (o) o[i] = f2e4m3(v * scale);
        s += v * v;
    }
    if (!do_sum) return;
    #pragma unroll
    for (int ofs = 16; ofs; ofs >>= 1) s += __shfl_xor_sync(0xFFFFFFFFu, s, ofs);
    __shared__ float ws[8];
    if ((threadIdx.x & 31) == 0) ws[threadIdx.x >> 5] = s;
    __syncthreads();
    if (threadIdx.x < 8) {
        float t = ws[threadIdx.x];
        #pragma unroll
        for (int ofs = 4; ofs; ofs >>= 1) t += __shfl_xor_sync(0xFFu, t, ofs);
        if (threadIdx.x == 0) atomicAdd(out, (float)(-0.5 / PRIOR_VAR) * t);
    }
}

// ----------------------------------------------------------------------------
// Fused head: logits = h2 @ W3^T + b3; sum log_softmax(logits)[Y].
// ----------------------------------------------------------------------------
__global__ __launch_bounds__(256)
void loss_kernel(const float* __restrict__ W3, const float* __restrict__ b3,
                 const int* __restrict__ Y, float* __restrict__ out)
{
    __shared__ __nv_bfloat16 sW[NC * H_];
    __shared__ float sSum;
    const int tid = threadIdx.x;
    if (tid == 0) sSum = 0.f;
    for (int i = tid; i < NC * H_; i += 256)
        sW[i] = __float2bfloat16(W3[i]);
    __syncthreads();

    const int lane = tid & 31, warp = tid >> 5;
    float local = 0.f;
    #pragma unroll
    for (int rr = 0; rr < 2; rr++) {
        int row = blockIdx.x * 16 + warp * 2 + rr;
        const __nv_bfloat16* hr = g_h2 + (size_t)row * H_;
        float acc[NC];
        #pragma unroll
        for (int c = 0; c < NC; c++) acc[c] = 0.f;
        #pragma unroll 4
        for (int i = 0; i < H_ / 64; i++) {
            int k = i * 64 + lane * 2;
            __nv_bfloat162 hv = *(const __nv_bfloat162*)(hr + k);
            float fx = __bfloat162float(hv.x);
            float fy = __bfloat162float(hv.y);
            #pragma unroll
            for (int c = 0; c < NC; c++) {
                __nv_bfloat162 wv = *(const __nv_bfloat162*)(sW + c * H_ + k);
                acc[c] += fx * __bfloat162float(wv.x) + fy * __bfloat162float(wv.y);
            }
        }
        #pragma unroll
        for (int c = 0; c < NC; c++) {
            #pragma unroll
            for (int o = 16; o; o >>= 1)
                acc[c] += __shfl_xor_sync(0xFFFFFFFFu, acc[c], o);
        }
        if (lane == 0) {
            float lg[NC];
            float m = -1e30f;
            #pragma unroll
            for (int c = 0; c < NC; c++) {
                lg[c] = acc[c] + b3[c];
                m = fmaxf(m, lg[c]);
            }
            float se = 0.f;
            #pragma unroll
            for (int c = 0; c < NC; c++) se += expf(lg[c] - m);
            local += lg[Y[row]] - (m + logf(se));
        }
    }
    if (lane == 0) atomicAdd(&sSum, local);
    __syncthreads();
    if (tid == 0) atomicAdd(out, sSum);
}

__global__ void init_out_kernel(float* out, float c) { out[0] = c; }

// ----------------------------------------------------------------------------
// kernel_launch  (order chosen so the big GEMM is launch index 5 for ncu -s 5)
// ----------------------------------------------------------------------------
extern "C" void kernel_launch(void* const* d_in, const int* in_sizes, int n_in,
                              void* d_out, int out_size)
{
    const float* X  = (const float*)d_in[0];
    const int*   Y  = (const int*)  d_in[1];
    const float* W1 = (const float*)d_in[2];
    const float* b1 = (const float*)d_in[3];
    const float* W2 = (const float*)d_in[4];
    const float* b2 = (const float*)d_in[5];
    const float* W3 = (const float*)d_in[6];
    const float* b3 = (const float*)d_in[7];
    float* out = (float*)d_out;

    cudaFuncSetAttribute(fp8_gemm_kernel,
                         cudaFuncAttributeMaxDynamicSharedMemorySize, SMEM_DYN);

    double d = 0.0;
    for (int i = 2; i < 8; i++) d += (double)in_sizes[i];
    float cterm = (float)(-0.5 * d * log(2.0 * M_PI * PRIOR_VAR));
    init_out_kernel<<<1, 1>>>(out, cterm);                              // 0

    auto conv_grid = [](int n) {
        int g = (n / 4 + 255) / 256;
        if (g < 1) g = 1;
        if (g > 4096) g = 4096;
        return g;
    };
    conv_sumsq_kernel<<<conv_grid(NS * INF_), 256>>>(X,  NS * INF_, 0, 1.0f,    0, out); // 1
    conv_sumsq_kernel<<<conv_grid(H_ * INF_), 256>>>(W1, H_ * INF_, 1, SCALE_W, 1, out); // 2
    conv_sumsq_kernel<<<conv_grid(H_ * H_),   256>>>(W2, H_ * H_,   2, SCALE_W, 1, out); // 3

    dim3 grid(H_ / BN, NS / BM);
    fp8_gemm_kernel<<<grid, 256, SMEM_DYN>>>(0, b1, INF_);              // 4
    fp8_gemm_kernel<<<grid, 256, SMEM_DYN>>>(1, b2, H_);                // 5 <- ncu

    conv_sumsq_kernel<<<conv_grid(in_sizes[3]), 256>>>(b1, in_sizes[3], 3, 0.f, 1, out);
    conv_sumsq_kernel<<<conv_grid(in_sizes[5]), 256>>>(b2, in_sizes[5], 3, 0.f, 1, out);
    conv_sumsq_kernel<<<conv_grid(in_sizes[6]), 256>>>(W3, in_sizes[6], 3, 0.f, 1, out);
    conv_sumsq_kernel<<<conv_grid(in_sizes[7]), 256>>>(b3, in_sizes[7], 3, 0.f, 1, out);

    loss_kernel<<<NS / 16, 256>>>(W3, b3, Y, out);
}

// round 5
// speedup vs baseline: 1.2557x; 1.0703x over previous
#include <cuda_runtime.h>
#include <cuda_bf16.h>
#include <cuda_fp16.h>
#include <cuda_fp8.h>
#include <math.h>
#include <stdint.h>

// ----------------------------------------------------------------------------
// Problem constants
// ----------------------------------------------------------------------------
#define NS   16384
#define INF_ 1024
#define H_   2048
#define NC   10
#define PRIOR_VAR 100.0

#define SCALE_W   64.0f
#define SCALE_H   8.0f
#define INV_G1    (1.0f / SCALE_W)
#define INV_G2    (1.0f / (SCALE_W * SCALE_H))

// ----------------------------------------------------------------------------
// Scratch (static device globals — no allocations allowed)
// ----------------------------------------------------------------------------
__device__ unsigned char g_Xq [NS * INF_];
__device__ unsigned char g_W1q[H_ * INF_];
__device__ unsigned char g_W2q[H_ * H_];
__device__ unsigned char g_h1q[(size_t)NS * H_];
__device__ __nv_bfloat16 g_h2 [(size_t)NS * H_];

// ----------------------------------------------------------------------------
// PTX helpers
// ----------------------------------------------------------------------------
__device__ __forceinline__ void cp16(uint32_t dst, const void* src) {
    asm volatile("cp.async.cg.shared.global [%0], [%1], 16;" :: "r"(dst), "l"(src));
}
__device__ __forceinline__ void cp_commit() {
    asm volatile("cp.async.commit_group;");
}
template<int N> __device__ __forceinline__ void cp_wait() {
    asm volatile("cp.async.wait_group %0;" :: "n"(N));
}
__device__ __forceinline__ void ldsm_x4(uint32_t* r, uint32_t addr) {
    asm volatile("ldmatrix.sync.aligned.m8n8.x4.shared.b16 {%0,%1,%2,%3}, [%4];"
                 : "=r"(r[0]), "=r"(r[1]), "=r"(r[2]), "=r"(r[3]) : "r"(addr));
}
__device__ __forceinline__ void mma_fp8_h(uint32_t* d, const uint32_t* a,
                                          const uint32_t* b) {
    asm volatile("mma.sync.aligned.m16n8k32.row.col.f16.e4m3.e4m3.f16 "
                 "{%0,%1}, {%2,%3,%4,%5}, {%6,%7}, {%0,%1};"
                 : "+r"(d[0]), "+r"(d[1])
                 : "r"(a[0]), "r"(a[1]), "r"(a[2]), "r"(a[3]),
                   "r"(b[0]), "r"(b[1]));
}
__device__ __forceinline__ unsigned char f2e4m3(float v) {
    return (unsigned char)__nv_cvt_float_to_fp8(v, __NV_SATFINITE, __NV_E4M3);
}

// ----------------------------------------------------------------------------
// FP8 GEMM (f16 accum) + bias + activation.
//   which=0: g_h1q = fp8(8 * relu(Xq @ W1q^T / 64 + b1))        K=1024
//   which=1: g_h2  = bf16(relu(h1q @ W2q^T / 512 + b2))         K=2048
// CTA 128x128, BK=64B, 3-stage cp.async, 8 warps (4x2, warp tile 32x64).
// Mainloop: batched LDSM (all fragments) then batched MMA — max MLP.
// ----------------------------------------------------------------------------
#define BM 128
#define BN 128
#define BK 64
#define STAGES 3
#define ROWB 80
#define HALF_STG (BM * ROWB)
#define STG_BYTES (2 * HALF_STG)
#define SMEM_DYN (STAGES * STG_BYTES)  // 61440

__global__ __launch_bounds__(256, 2)
void fp8_gemm_kernel(int which, const float* __restrict__ bias, int K)
{
    extern __shared__ unsigned char smem[];
    const unsigned char* __restrict__ A = (which == 0) ? g_Xq  : g_h1q;
    const unsigned char* __restrict__ B = (which == 0) ? g_W1q : g_W2q;

    uint32_t sb;
    asm("{ .reg .u64 t; cvta.to.shared.u64 t, %1; cvt.u32.u64 %0, t; }"
        : "=r"(sb) : "l"(smem));

    const int tid  = threadIdx.x;
    const int lane = tid & 31;
    const int warp = tid >> 5;
    const int wm   = warp >> 1;
    const int wn   = warp & 1;
    const int bm   = blockIdx.y * BM;
    const int bn   = blockIdx.x * BN;

    uint32_t acc[2][8][2];
    #pragma unroll
    for (int i = 0; i < 2; i++)
        #pragma unroll
        for (int j = 0; j < 8; j++) { acc[i][j][0] = 0u; acc[i][j][1] = 0u; }

    const int KT = K / BK;

    auto load_stage = [&](int st, int kt) {
        uint32_t aB = sb + st * STG_BYTES;
        uint32_t bB = aB + HALF_STG;
        const unsigned char* Ap = A + (size_t)bm * K + kt * BK;
        const unsigned char* Bp = B + (size_t)bn * K + kt * BK;
        #pragma unroll
        for (int q = 0; q < 2; q++) {
            int idx = tid + q * 256;
            int r = idx >> 2, c = (idx & 3) * 16;
            cp16(aB + r * ROWB + c, Ap + (size_t)r * K + c);
            cp16(bB + r * ROWB + c, Bp + (size_t)r * K + c);
        }
    };

    #pragma unroll
    for (int p = 0; p < STAGES - 1; p++) { load_stage(p, p); cp_commit(); }

    // Precomputed per-lane LDSM offsets (within a stage).
    // A (x4): lanes 0-15 rows of 16x(ks*32) block at +0/+16 col by lane>>4.
    const int aRow = wm * 32 + (lane & 15);
    const int aCol = (lane >> 4) * 16;
    const uint32_t aOff0 = (uint32_t)(aRow * ROWB + aCol);          // mi=0
    const uint32_t aOff1 = (uint32_t)((aRow + 16) * ROWB + aCol);   // mi=1
    // B (x4): lane -> n row = njp*16 + ((lane>>4)&1)*8 + (lane&7),
    //         k col = ((lane>>3)&1)*16. Covers nj pair (2njp, 2njp+1).
    const int bRow = wn * 64 + ((lane >> 4) & 1) * 8 + (lane & 7);
    const int bCol = ((lane >> 3) & 1) * 16;
    const uint32_t bOffBase = (uint32_t)(bRow * ROWB + bCol);

    for (int i = 0; i < KT; i++) {
        const int s = i % STAGES;
        cp_wait<STAGES - 2>();
        __syncthreads();
        if (i + STAGES - 1 < KT) load_stage((i + STAGES - 1) % STAGES, i + STAGES - 1);
        cp_commit();

        const uint32_t aBase = sb + s * STG_BYTES;
        const uint32_t bBase = aBase + HALF_STG;
        #pragma unroll
        for (int ks = 0; ks < 2; ks++) {
            // ---- batched LDSM: 6 back-to-back loads, MLP=6 ----
            uint32_t aF[2][4];
            uint32_t bF[4][4];
            ldsm_x4(aF[0], aBase + ks * 32 + aOff0);
            ldsm_x4(aF[1], aBase + ks * 32 + aOff1);
            #pragma unroll
            for (int njp = 0; njp < 4; njp++)
                ldsm_x4(bF[njp], bBase + ks * 32 + bOffBase + njp * 16 * ROWB);
            // ---- batched MMA: 16 dependency-free issues ----
            #pragma unroll
            for (int njp = 0; njp < 4; njp++) {
                #pragma unroll
                for (int h = 0; h < 2; h++) {
                    mma_fp8_h(acc[0][njp * 2 + h], aF[0], &bF[njp][2 * h]);
                    mma_fp8_h(acc[1][njp * 2 + h], aF[1], &bF[njp][2 * h]);
                }
            }
        }
    }

    // epilogue
    const float inv = (which == 0) ? INV_G1 : INV_G2;
    #pragma unroll
    for (int mi = 0; mi < 2; mi++) {
        int row0 = bm + wm * 32 + mi * 16 + (lane >> 2);
        #pragma unroll
        for (int nj = 0; nj < 8; nj++) {
            int col = bn + wn * 64 + nj * 8 + 2 * (lane & 3);
            float bv0 = __ldg(bias + col), bv1 = __ldg(bias + col + 1);
            float2 f01 = __half22float2(*(const __half2*)&acc[mi][nj][0]);
            float2 f23 = __half22float2(*(const __half2*)&acc[mi][nj][1]);
            float v0 = fmaxf(f01.x * inv + bv0, 0.f);
            float v1 = fmaxf(f01.y * inv + bv1, 0.f);
            float v2 = fmaxf(f23.x * inv + bv0, 0.f);
            float v3 = fmaxf(f23.y * inv + bv1, 0.f);
            if (which == 0) {
                unsigned short p0 = (unsigned short)f2e4m3(v0 * SCALE_H) |
                                    ((unsigned short)f2e4m3(v1 * SCALE_H) << 8);
                unsigned short p1 = (unsigned short)f2e4m3(v2 * SCALE_H) |
                                    ((unsigned short)f2e4m3(v3 * SCALE_H) << 8);
                *(unsigned short*)(g_h1q + (size_t)row0 * H_ + col)       = p0;
                *(unsigned short*)(g_h1q + (size_t)(row0 + 8) * H_ + col) = p1;
            } else {
                *(__nv_bfloat162*)(g_h2 + (size_t)row0 * H_ + col) =
                    __floats2bfloat162_rn(v0, v1);
                *(__nv_bfloat162*)(g_h2 + (size_t)(row0 + 8) * H_ + col) =
                    __floats2bfloat162_rn(v2, v3);
            }
        }
    }
}

// ----------------------------------------------------------------------------
// Fused fp32 -> fp8 convert (with scale) + optional prior sum-of-squares.
// ----------------------------------------------------------------------------
__global__ void conv_sumsq_kernel(const float* __restrict__ in, int n,
                                  int dst, float scale, int do_sum,
                                  float* __restrict__ out)
{
    unsigned char* o = (dst == 0) ? g_Xq : (dst == 1) ? g_W1q
                     : (dst == 2) ? g_W2q : nullptr;
    float s = 0.f;
    const int gsz = gridDim.x * blockDim.x;
    const int gt  = blockIdx.x * blockDim.x + threadIdx.x;
    const int n4  = n >> 2;
    for (int i = gt; i < n4; i += gsz) {
        float4 v = ((const float4*)in)[i];
        if (o) {
            uint32_t p = (uint32_t)f2e4m3(v.x * scale)
                       | ((uint32_t)f2e4m3(v.y * scale) << 8)
                       | ((uint32_t)f2e4m3(v.z * scale) << 16)
                       | ((uint32_t)f2e4m3(v.w * scale) << 24);
            ((uint32_t*)o)[i] = p;
        }
        s += v.x * v.x + v.y * v.y + v.z * v.z + v.w * v.w;
    }
    for (int i = 4 * n4 + gt; i < n; i += gsz) {
        float v = in[i];
        if (o) o[i] = f2e4m3(v * scale);
        s += v * v;
    }
    if (!do_sum) return;
    #pragma unroll
    for (int ofs = 16; ofs; ofs >>= 1) s += __shfl_xor_sync(0xFFFFFFFFu, s, ofs);
    __shared__ float ws[8];
    if ((threadIdx.x & 31) == 0) ws[threadIdx.x >> 5] = s;
    __syncthreads();
    if (threadIdx.x < 8) {
        float t = ws[threadIdx.x];
        #pragma unroll
        for (int ofs = 4; ofs; ofs >>= 1) t += __shfl_xor_sync(0xFFu, t, ofs);
        if (threadIdx.x == 0) atomicAdd(out, (float)(-0.5 / PRIOR_VAR) * t);
    }
}

// ----------------------------------------------------------------------------
// Fused head: logits = h2 @ W3^T + b3; sum log_softmax(logits)[Y].
// ----------------------------------------------------------------------------
__global__ __launch_bounds__(256)
void loss_kernel(const float* __restrict__ W3, const float* __restrict__ b3,
                 const int* __restrict__ Y, float* __restrict__ out)
{
    __shared__ __nv_bfloat16 sW[NC * H_];
    __shared__ float sSum;
    const int tid = threadIdx.x;
    if (tid == 0) sSum = 0.f;
    for (int i = tid; i < NC * H_; i += 256)
        sW[i] = __float2bfloat16(W3[i]);
    __syncthreads();

    const int lane = tid & 31, warp = tid >> 5;
    float local = 0.f;
    #pragma unroll
    for (int rr = 0; rr < 2; rr++) {
        int row = blockIdx.x * 16 + warp * 2 + rr;
        const __nv_bfloat16* hr = g_h2 + (size_t)row * H_;
        float acc[NC];
        #pragma unroll
        for (int c = 0; c < NC; c++) acc[c] = 0.f;
        #pragma unroll 4
        for (int i = 0; i < H_ / 64; i++) {
            int k = i * 64 + lane * 2;
            __nv_bfloat162 hv = *(const __nv_bfloat162*)(hr + k);
            float fx = __bfloat162float(hv.x);
            float fy = __bfloat162float(hv.y);
            #pragma unroll
            for (int c = 0; c < NC; c++) {
                __nv_bfloat162 wv = *(const __nv_bfloat162*)(sW + c * H_ + k);
                acc[c] += fx * __bfloat162float(wv.x) + fy * __bfloat162float(wv.y);
            }
        }
        #pragma unroll
        for (int c = 0; c < NC; c++) {
            #pragma unroll
            for (int o = 16; o; o >>= 1)
                acc[c] += __shfl_xor_sync(0xFFFFFFFFu, acc[c], o);
        }
        if (lane == 0) {
            float lg[NC];
            float m = -1e30f;
            #pragma unroll
            for (int c = 0; c < NC; c++) {
                lg[c] = acc[c] + b3[c];
                m = fmaxf(m, lg[c]);
            }
            float se = 0.f;
            #pragma unroll
            for (int c = 0; c < NC; c++) se += expf(lg[c] - m);
            local += lg[Y[row]] - (m + logf(se));
        }
    }
    if (lane == 0) atomicAdd(&sSum, local);
    __syncthreads();
    if (tid == 0) atomicAdd(out, sSum);
}

__global__ void init_out_kernel(float* out, float c) { out[0] = c; }

// ----------------------------------------------------------------------------
// kernel_launch
// ----------------------------------------------------------------------------
extern "C" void kernel_launch(void* const* d_in, const int* in_sizes, int n_in,
                              void* d_out, int out_size)
{
    const float* X  = (const float*)d_in[0];
    const int*   Y  = (const int*)  d_in[1];
    const float* W1 = (const float*)d_in[2];
    const float* b1 = (const float*)d_in[3];
    const float* W2 = (const float*)d_in[4];
    const float* b2 = (const float*)d_in[5];
    const float* W3 = (const float*)d_in[6];
    const float* b3 = (const float*)d_in[7];
    float* out = (float*)d_out;

    cudaFuncSetAttribute(fp8_gemm_kernel,
                         cudaFuncAttributeMaxDynamicSharedMemorySize, SMEM_DYN);

    double d = 0.0;
    for (int i = 2; i < 8; i++) d += (double)in_sizes[i];
    float cterm = (float)(-0.5 * d * log(2.0 * M_PI * PRIOR_VAR));
    init_out_kernel<<<1, 1>>>(out, cterm);                              // 0

    auto conv_grid = [](int n) {
        int g = (n / 4 + 255) / 256;
        if (g < 1) g = 1;
        if (g > 4096) g = 4096;
        return g;
    };
    conv_sumsq_kernel<<<conv_grid(NS * INF_), 256>>>(X,  NS * INF_, 0, 1.0f,    0, out); // 1
    conv_sumsq_kernel<<<conv_grid(H_ * INF_), 256>>>(W1, H_ * INF_, 1, SCALE_W, 1, out); // 2
    conv_sumsq_kernel<<<conv_grid(H_ * H_),   256>>>(W2, H_ * H_,   2, SCALE_W, 1, out); // 3

    dim3 grid(H_ / BN, NS / BM);
    fp8_gemm_kernel<<<grid, 256, SMEM_DYN>>>(0, b1, INF_);              // 4
    fp8_gemm_kernel<<<grid, 256, SMEM_DYN>>>(1, b2, H_);                // 5

    conv_sumsq_kernel<<<conv_grid(in_sizes[3]), 256>>>(b1, in_sizes[3], 3, 0.f, 1, out);
    conv_sumsq_kernel<<<conv_grid(in_sizes[5]), 256>>>(b2, in_sizes[5], 3, 0.f, 1, out);
    conv_sumsq_kernel<<<conv_grid(in_sizes[6]), 256>>>(W3, in_sizes[6], 3, 0.f, 1, out);
    conv_sumsq_kernel<<<conv_grid(in_sizes[7]), 256>>>(b3, in_sizes[7], 3, 0.f, 1, out);

    loss_kernel<<<NS / 16, 256>>>(W3, b3, Y, out);
}

// round 6
// speedup vs baseline: 1.2795x; 1.0189x over previous
#include <cuda_runtime.h>
#include <cuda_bf16.h>
#include <cuda_fp16.h>
#include <cuda_fp8.h>
#include <math.h>
#include <stdint.h>

// ----------------------------------------------------------------------------
// Problem constants
// ----------------------------------------------------------------------------
#define NS   16384
#define INF_ 1024
#define H_   2048
#define NC   10
#define PRIOR_VAR 100.0

#define SCALE_W   64.0f
#define SCALE_H   8.0f
#define INV_G1    (1.0f / SCALE_W)
#define INV_G2    (1.0f / (SCALE_W * SCALE_H))

// ----------------------------------------------------------------------------
// Scratch (static device globals — no allocations allowed)
// ----------------------------------------------------------------------------
__device__ unsigned char g_Xq [NS * INF_];
__device__ unsigned char g_W1q[H_ * INF_];
__device__ unsigned char g_W2q[H_ * H_];
__device__ unsigned char g_h1q[(size_t)NS * H_];
__device__ __nv_bfloat16 g_h2 [(size_t)NS * H_];

// ----------------------------------------------------------------------------
// PTX helpers
// ----------------------------------------------------------------------------
__device__ __forceinline__ void cp16(uint32_t dst, const void* src) {
    asm volatile("cp.async.cg.shared.global [%0], [%1], 16;" :: "r"(dst), "l"(src));
}
__device__ __forceinline__ void cp_commit() {
    asm volatile("cp.async.commit_group;");
}
template<int N> __device__ __forceinline__ void cp_wait() {
    asm volatile("cp.async.wait_group %0;" :: "n"(N));
}
__device__ __forceinline__ void ldsm_x4(uint32_t* r, uint32_t addr) {
    asm volatile("ldmatrix.sync.aligned.m8n8.x4.shared.b16 {%0,%1,%2,%3}, [%4];"
                 : "=r"(r[0]), "=r"(r[1]), "=r"(r[2]), "=r"(r[3]) : "r"(addr));
}
__device__ __forceinline__ void mma_fp8_h(uint32_t* d, const uint32_t* a,
                                          const uint32_t* b) {
    asm volatile("mma.sync.aligned.m16n8k32.row.col.f16.e4m3.e4m3.f16 "
                 "{%0,%1}, {%2,%3,%4,%5}, {%6,%7}, {%0,%1};"
                 : "+r"(d[0]), "+r"(d[1])
                 : "r"(a[0]), "r"(a[1]), "r"(a[2]), "r"(a[3]),
                   "r"(b[0]), "r"(b[1]));
}
__device__ __forceinline__ unsigned char f2e4m3(float v) {
    return (unsigned char)__nv_cvt_float_to_fp8(v, __NV_SATFINITE, __NV_E4M3);
}

// ----------------------------------------------------------------------------
// FP8 GEMM (f16 accum) + bias + activation.
//   which=0: g_h1q = fp8(8 * relu(Xq @ W1q^T / 64 + b1))        K=1024
//   which=1: g_h2  = bf16(relu(h1q @ W2q^T / 512 + b2))         K=2048
// CTA 256x128, BK=64B, 3-stage cp.async, 8 warps (4m x 2n, warp tile 64x64).
// ----------------------------------------------------------------------------
#define BM 256
#define BN 128
#define BK 64
#define STAGES 3
#define ROWB 80
#define A_STG (BM * ROWB)              // 20480
#define B_STG (BN * ROWB)              // 10240
#define STG_BYTES (A_STG + B_STG)      // 30720
#define SMEM_DYN (STAGES * STG_BYTES)  // 92160

__global__ __launch_bounds__(256, 2)
void fp8_gemm_kernel(int which, const float* __restrict__ bias, int K)
{
    extern __shared__ unsigned char smem[];
    const unsigned char* __restrict__ A = (which == 0) ? g_Xq  : g_h1q;
    const unsigned char* __restrict__ B = (which == 0) ? g_W1q : g_W2q;

    uint32_t sb;
    asm("{ .reg .u64 t; cvta.to.shared.u64 t, %1; cvt.u32.u64 %0, t; }"
        : "=r"(sb) : "l"(smem));

    const int tid  = threadIdx.x;
    const int lane = tid & 31;
    const int warp = tid >> 5;
    const int wm   = warp >> 1;           // 0..3 -> 64-row slice
    const int wn   = warp & 1;            // 0..1 -> 64-col slice
    const int bm   = blockIdx.y * BM;
    const int bn   = blockIdx.x * BN;

    uint32_t acc[4][8][2];                // f16x2 accumulators (64 regs)
    #pragma unroll
    for (int i = 0; i < 4; i++)
        #pragma unroll
        for (int j = 0; j < 8; j++) { acc[i][j][0] = 0u; acc[i][j][1] = 0u; }

    const int KT = K / BK;

    // stage: A 256 rows x 64B (1024 chunks) + B 128 rows x 64B (512 chunks)
    auto load_stage = [&](int st, int kt) {
        uint32_t aB = sb + st * STG_BYTES;
        uint32_t bB = aB + A_STG;
        const unsigned char* Ap = A + (size_t)bm * K + kt * BK;
        const unsigned char* Bp = B + (size_t)bn * K + kt * BK;
        #pragma unroll
        for (int q = 0; q < 4; q++) {
            int idx = tid + q * 256;
            int r = idx >> 2, c = (idx & 3) * 16;
            cp16(aB + r * ROWB + c, Ap + (size_t)r * K + c);
        }
        #pragma unroll
        for (int q = 0; q < 2; q++) {
            int idx = tid + q * 256;
            int r = idx >> 2, c = (idx & 3) * 16;
            cp16(bB + r * ROWB + c, Bp + (size_t)r * K + c);
        }
    };

    #pragma unroll
    for (int p = 0; p < STAGES - 1; p++) { load_stage(p, p); cp_commit(); }

    // per-lane LDSM offsets within stage
    // A rows: wm*64 + mi*16 + (lane&15), col (lane>>4)*16 (+ks*32)
    const uint32_t aOffBase =
        (uint32_t)((wm * 64 + (lane & 15)) * ROWB + (lane >> 4) * 16);
    // B rows (= n cols): wn*64 + njp*16 + ((lane>>4)&1)*8 + (lane&7),
    // col ((lane>>3)&1)*16 (+ks*32); x4 covers nj pair (2njp, 2njp+1)
    const uint32_t bOffBase =
        (uint32_t)((wn * 64 + ((lane >> 4) & 1) * 8 + (lane & 7)) * ROWB +
                   ((lane >> 3) & 1) * 16);

    for (int i = 0; i < KT; i++) {
        const int s = i % STAGES;
        cp_wait<STAGES - 2>();
        __syncthreads();
        if (i + STAGES - 1 < KT) load_stage((i + STAGES - 1) % STAGES, i + STAGES - 1);
        cp_commit();

        const uint32_t aBase = sb + s * STG_BYTES;
        const uint32_t bBase = aBase + A_STG;
        #pragma unroll
        for (int ks = 0; ks < 2; ks++) {
            uint32_t aF[4][4];
            uint32_t bF[4][4];
            #pragma unroll
            for (int mi = 0; mi < 4; mi++)
                ldsm_x4(aF[mi], aBase + ks * 32 + aOffBase + mi * 16 * ROWB);
            #pragma unroll
            for (int njp = 0; njp < 4; njp++)
                ldsm_x4(bF[njp], bBase + ks * 32 + bOffBase + njp * 16 * ROWB);
            #pragma unroll
            for (int njp = 0; njp < 4; njp++) {
                #pragma unroll
                for (int h = 0; h < 2; h++) {
                    #pragma unroll
                    for (int mi = 0; mi < 4; mi++)
                        mma_fp8_h(acc[mi][njp * 2 + h], aF[mi], &bF[njp][2 * h]);
                }
            }
        }
    }

    // epilogue
    const float inv = (which == 0) ? INV_G1 : INV_G2;
    #pragma unroll
    for (int mi = 0; mi < 4; mi++) {
        int row0 = bm + wm * 64 + mi * 16 + (lane >> 2);
        #pragma unroll
        for (int nj = 0; nj < 8; nj++) {
            int col = bn + wn * 64 + nj * 8 + 2 * (lane & 3);
            float bv0 = __ldg(bias + col), bv1 = __ldg(bias + col + 1);
            float2 f01 = __half22float2(*(const __half2*)&acc[mi][nj][0]);
            float2 f23 = __half22float2(*(const __half2*)&acc[mi][nj][1]);
            float v0 = fmaxf(f01.x * inv + bv0, 0.f);
            float v1 = fmaxf(f01.y * inv + bv1, 0.f);
            float v2 = fmaxf(f23.x * inv + bv0, 0.f);
            float v3 = fmaxf(f23.y * inv + bv1, 0.f);
            if (which == 0) {
                unsigned short p0 = (unsigned short)f2e4m3(v0 * SCALE_H) |
                                    ((unsigned short)f2e4m3(v1 * SCALE_H) << 8);
                unsigned short p1 = (unsigned short)f2e4m3(v2 * SCALE_H) |
                                    ((unsigned short)f2e4m3(v3 * SCALE_H) << 8);
                *(unsigned short*)(g_h1q + (size_t)row0 * H_ + col)       = p0;
                *(unsigned short*)(g_h1q + (size_t)(row0 + 8) * H_ + col) = p1;
            } else {
                *(__nv_bfloat162*)(g_h2 + (size_t)row0 * H_ + col) =
                    __floats2bfloat162_rn(v0, v1);
                *(__nv_bfloat162*)(g_h2 + (size_t)(row0 + 8) * H_ + col) =
                    __floats2bfloat162_rn(v2, v3);
            }
        }
    }
}

// ----------------------------------------------------------------------------
// Fused fp32 -> fp8 convert (with scale) + optional prior sum-of-squares.
// ----------------------------------------------------------------------------
__global__ void conv_sumsq_kernel(const float* __restrict__ in, int n,
                                  int dst, float scale, int do_sum,
                                  float* __restrict__ out)
{
    unsigned char* o = (dst == 0) ? g_Xq : (dst == 1) ? g_W1q
                     : (dst == 2) ? g_W2q : nullptr;
    float s = 0.f;
    const int gsz = gridDim.x * blockDim.x;
    const int gt  = blockIdx.x * blockDim.x + threadIdx.x;
    const int n4  = n >> 2;
    for (int i = gt; i < n4; i += gsz) {
        float4 v = ((const float4*)in)[i];
        if (o) {
            uint32_t p = (uint32_t)f2e4m3(v.x * scale)
                       | ((uint32_t)f2e4m3(v.y * scale) << 8)
                       | ((uint32_t)f2e4m3(v.z * scale) << 16)
                       | ((uint32_t)f2e4m3(v.w * scale) << 24);
            ((uint32_t*)o)[i] = p;
        }
        s += v.x * v.x + v.y * v.y + v.z * v.z + v.w * v.w;
    }
    for (int i = 4 * n4 + gt; i < n; i += gsz) {
        float v = in[i];
        if (o) o[i] = f2e4m3(v * scale);
        s += v * v;
    }
    if (!do_sum) return;
    #pragma unroll
    for (int ofs = 16; ofs; ofs >>= 1) s += __shfl_xor_sync(0xFFFFFFFFu, s, ofs);
    __shared__ float ws[8];
    if ((threadIdx.x & 31) == 0) ws[threadIdx.x >> 5] = s;
    __syncthreads();
    if (threadIdx.x < 8) {
        float t = ws[threadIdx.x];
        #pragma unroll
        for (int ofs = 4; ofs; ofs >>= 1) t += __shfl_xor_sync(0xFFu, t, ofs);
        if (threadIdx.x == 0) atomicAdd(out, (float)(-0.5 / PRIOR_VAR) * t);
    }
}

// ----------------------------------------------------------------------------
// Fused head: logits = h2 @ W3^T + b3; sum log_softmax(logits)[Y].
// ----------------------------------------------------------------------------
__global__ __launch_bounds__(256)
void loss_kernel(const float* __restrict__ W3, const float* __restrict__ b3,
                 const int* __restrict__ Y, float* __restrict__ out)
{
    __shared__ __nv_bfloat16 sW[NC * H_];
    __shared__ float sSum;
    const int tid = threadIdx.x;
    if (tid == 0) sSum = 0.f;
    for (int i = tid; i < NC * H_; i += 256)
        sW[i] = __float2bfloat16(W3[i]);
    __syncthreads();

    const int lane = tid & 31, warp = tid >> 5;
    float local = 0.f;
    #pragma unroll
    for (int rr = 0; rr < 2; rr++) {
        int row = blockIdx.x * 16 + warp * 2 + rr;
        const __nv_bfloat16* hr = g_h2 + (size_t)row * H_;
        float acc[NC];
        #pragma unroll
        for (int c = 0; c < NC; c++) acc[c] = 0.f;
        #pragma unroll 4
        for (int i = 0; i < H_ / 64; i++) {
            int k = i * 64 + lane * 2;
            __nv_bfloat162 hv = *(const __nv_bfloat162*)(hr + k);
            float fx = __bfloat162float(hv.x);
            float fy = __bfloat162float(hv.y);
            #pragma unroll
            for (int c = 0; c < NC; c++) {
                __nv_bfloat162 wv = *(const __nv_bfloat162*)(sW + c * H_ + k);
                acc[c] += fx * __bfloat162float(wv.x) + fy * __bfloat162float(wv.y);
            }
        }
        #pragma unroll
        for (int c = 0; c < NC; c++) {
            #pragma unroll
            for (int o = 16; o; o >>= 1)
                acc[c] += __shfl_xor_sync(0xFFFFFFFFu, acc[c], o);
        }
        if (lane == 0) {
            float lg[NC];
            float m = -1e30f;
            #pragma unroll
            for (int c = 0; c < NC; c++) {
                lg[c] = acc[c] + b3[c];
                m = fmaxf(m, lg[c]);
            }
            float se = 0.f;
            #pragma unroll
            for (int c = 0; c < NC; c++) se += expf(lg[c] - m);
            local += lg[Y[row]] - (m + logf(se));
        }
    }
    if (lane == 0) atomicAdd(&sSum, local);
    __syncthreads();
    if (tid == 0) atomicAdd(out, sSum);
}

__global__ void init_out_kernel(float* out, float c) { out[0] = c; }

// ----------------------------------------------------------------------------
// kernel_launch
// ----------------------------------------------------------------------------
extern "C" void kernel_launch(void* const* d_in, const int* in_sizes, int n_in,
                              void* d_out, int out_size)
{
    const float* X  = (const float*)d_in[0];
    const int*   Y  = (const int*)  d_in[1];
    const float* W1 = (const float*)d_in[2];
    const float* b1 = (const float*)d_in[3];
    const float* W2 = (const float*)d_in[4];
    const float* b2 = (const float*)d_in[5];
    const float* W3 = (const float*)d_in[6];
    const float* b3 = (const float*)d_in[7];
    float* out = (float*)d_out;

    cudaFuncSetAttribute(fp8_gemm_kernel,
                         cudaFuncAttributeMaxDynamicSharedMemorySize, SMEM_DYN);

    double d = 0.0;
    for (int i = 2; i < 8; i++) d += (double)in_sizes[i];
    float cterm = (float)(-0.5 * d * log(2.0 * M_PI * PRIOR_VAR));
    init_out_kernel<<<1, 1>>>(out, cterm);                              // 0

    auto conv_grid = [](int n) {
        int g = (n / 4 + 255) / 256;
        if (g < 1) g = 1;
        if (g > 4096) g = 4096;
        return g;
    };
    conv_sumsq_kernel<<<conv_grid(NS * INF_), 256>>>(X,  NS * INF_, 0, 1.0f,    0, out); // 1
    conv_sumsq_kernel<<<conv_grid(H_ * INF_), 256>>>(W1, H_ * INF_, 1, SCALE_W, 1, out); // 2
    conv_sumsq_kernel<<<conv_grid(H_ * H_),   256>>>(W2, H_ * H_,   2, SCALE_W, 1, out); // 3

    dim3 grid(H_ / BN, NS / BM);   // (16, 64)
    fp8_gemm_kernel<<<grid, 256, SMEM_DYN>>>(0, b1, INF_);              // 4
    fp8_gemm_kernel<<<grid, 256, SMEM_DYN>>>(1, b2, H_);                // 5

    conv_sumsq_kernel<<<conv_grid(in_sizes[3]), 256>>>(b1, in_sizes[3], 3, 0.f, 1, out);
    conv_sumsq_kernel<<<conv_grid(in_sizes[5]), 256>>>(b2, in_sizes[5], 3, 0.f, 1, out);
    conv_sumsq_kernel<<<conv_grid(in_sizes[6]), 256>>>(W3, in_sizes[6], 3, 0.f, 1, out);
    conv_sumsq_kernel<<<conv_grid(in_sizes[7]), 256>>>(b3, in_sizes[7], 3, 0.f, 1, out);

    loss_kernel<<<NS / 16, 256>>>(W3, b3, Y, out);
}